// round 2
// baseline (speedup 1.0000x reference)
#include <cuda_runtime.h>

#define FULL 0xffffffffu

// softmax over 16-lane groups of (100 * x), x one value per lane.
__device__ __forceinline__ float softmax16(float x) {
    float m = x;
    m = fmaxf(m, __shfl_xor_sync(FULL, m, 1));
    m = fmaxf(m, __shfl_xor_sync(FULL, m, 2));
    m = fmaxf(m, __shfl_xor_sync(FULL, m, 4));
    m = fmaxf(m, __shfl_xor_sync(FULL, m, 8));
    float e = __expf(100.f * (x - m));
    float s = e;
    s += __shfl_xor_sync(FULL, s, 1);
    s += __shfl_xor_sync(FULL, s, 2);
    s += __shfl_xor_sync(FULL, s, 4);
    s += __shfl_xor_sync(FULL, s, 8);
    return __fdividef(e, s);
}

// Linear convolution r[t] = sum_{i+j=t} pa[i]*pb[j]  (t = 0..30, r[31]=0),
// where p holds pa on lanes 0..15 and pb on lanes 16..31.
// Outputs: u[s] = r[s]+r[s+16], v[s] = r[s-1]+r[s+15] (lanes 0..15),
//          R0 = sum_{t>=16} r[t], R1 = R0 + r[15]  (all lanes).
// sPad[0..46] must be zero outside [15..30]; we write pa into [15..30].
__device__ __forceinline__ void conv16(float p, float* sPad, int lane,
                                       float& u, float& v, float& R0, float& R1) {
    __syncwarp();                      // prior readers of sPad done
    if (lane < 16) sPad[15 + lane] = p;
    __syncwarp();
    float r = 0.f;
#pragma unroll
    for (int j = 0; j < 16; j++) {
        float pbj = __shfl_sync(FULL, p, 16 + j);
        r = fmaf(sPad[lane - j + 15], pbj, r);   // conflict-free, zero-padded
    }
    u = r + __shfl_down_sync(FULL, r, 16);
    float rm1 = __shfl_up_sync(FULL, r, 1);
    if (lane == 0) rm1 = 0.f;
    float rp15 = __shfl_sync(FULL, r, (lane + 15) & 31);
    v = rm1 + rp15;
    float t = (lane >= 16) ? r : 0.f;
    t += __shfl_xor_sync(FULL, t, 16);
    t += __shfl_xor_sync(FULL, t, 8);
    t += __shfl_xor_sync(FULL, t, 4);
    t += __shfl_xor_sync(FULL, t, 2);
    t += __shfl_xor_sync(FULL, t, 1);
    R0 = t;
    R1 = t + __shfl_sync(FULL, r, 15);
}

// One warp per batch element. 8 warps / block.
__global__ void __launch_bounds__(256) nalu_kernel(
        const float* __restrict__ A, const float* __restrict__ Bq,
        float* __restrict__ O, int B) {
    __shared__ float smem[8 * 576];
    const int warpId = threadIdx.x >> 5;
    const int lane = threadIdx.x & 31;
    const int n = blockIdx.x * 8 + warpId;
    if (n >= B) return;

    float* ws  = smem + warpId * 576;
    float* sA  = ws;           // 256 floats
    float* sB  = ws + 272;     // 256 floats, +16-bank offset vs sA (conflict-free)
    float* sPad = ws + 528;    // 47 floats, zero-padded conv buffer

    // zero the pad buffer once (entries [15..30] get overwritten per conv)
    sPad[lane] = 0.f;
    if (lane < 15) sPad[32 + lane] = 0.f;

    float uL[4], vL[4], R0L[4], R1L[4];
    float uH[4], vH[4], R0H[4], R1H[4];

    const float4* a4 = (const float4*)(A + (size_t)n * 1024);
    const float4* b4 = (const float4*)(Bq + (size_t)n * 1024);
    const int l = lane & 15;
    const float* hbase = (lane < 16) ? sA : sB;  // lanes 0-15: a-side, 16-31: b-side

#pragma unroll
    for (int i = 0; i < 4; i++) {
        // ---- stage a[n,i,:], b[n,i,:] into smem (coalesced float4) ----
        float4 av0 = a4[i * 64 + lane];
        float4 av1 = a4[i * 64 + 32 + lane];
        float4 bv0 = b4[i * 64 + lane];
        float4 bv1 = b4[i * 64 + 32 + lane];
        __syncwarp();                         // previous byte's readers done
        ((float4*)sA)[lane]      = av0;
        ((float4*)sA)[32 + lane] = av1;
        ((float4*)sB)[lane]      = bv0;
        ((float4*)sB)[32 + lane] = bv1;
        __syncwarp();

        // ---- nibble sums: hv = high[l], lv = low[l] (a on lanes<16, b on >=16) ----
        float hv = 0.f, lv = 0.f;
#pragma unroll
        for (int k = 0; k < 16; k++) hv += hbase[l * 16 + ((k + l) & 15)]; // rotated: conflict-free
#pragma unroll
        for (int k = 0; k < 16; k++) lv += hbase[k * 16 + l];              // conflict-free

        float ph = softmax16(hv);   // pah | pbh across the two halves
        float pl = softmax16(lv);   // pal | pbl

        conv16(pl, sPad, lane, uL[i], vL[i], R0L[i], R1L[i]);
        conv16(ph, sPad, lane, uH[i], vH[i], R0H[i], R1H[i]);
    }

    // ---- serial ripple-carry chain (8 scalar stages) + outputs ----
    float c1 = 0.f;  // P(carry=1); carry starts at one-hot [1,0]
    float* orow = O + (size_t)n * 1024 + lane * 8;
#pragma unroll
    for (int i = 0; i < 4; i++) {
        // low-nibble add
        float pc1 = __fdividef(1.f, 1.f + __expf(100.f * (1.f - 2.f * c1)));
        float pc0 = 1.f - pc1;
        float sl = fmaf(pc0, uL[i], pc1 * vL[i]);
        c1 = fmaf(pc0, R0L[i], pc1 * R1L[i]);
        // high-nibble add
        pc1 = __fdividef(1.f, 1.f + __expf(100.f * (1.f - 2.f * c1)));
        pc0 = 1.f - pc1;
        float sh = fmaf(pc0, uH[i], pc1 * vH[i]);
        c1 = fmaf(pc0, R0H[i], pc1 * R1H[i]);

        // n2b: out[h*16+l] = softmax16(100*sh)[h] * softmax16(100*sl)[l]
        float psl = softmax16(sl);
        float psh = softmax16(sh);

        float hvv = __shfl_sync(FULL, psh, lane >> 1);  // lane covers h = lane/2
        int lb = (lane & 1) * 8;                        // l in [lb, lb+8)
        float4 o0, o1;
        o0.x = hvv * __shfl_sync(FULL, psl, lb + 0);
        o0.y = hvv * __shfl_sync(FULL, psl, lb + 1);
        o0.z = hvv * __shfl_sync(FULL, psl, lb + 2);
        o0.w = hvv * __shfl_sync(FULL, psl, lb + 3);
        o1.x = hvv * __shfl_sync(FULL, psl, lb + 4);
        o1.y = hvv * __shfl_sync(FULL, psl, lb + 5);
        o1.z = hvv * __shfl_sync(FULL, psl, lb + 6);
        o1.w = hvv * __shfl_sync(FULL, psl, lb + 7);
        ((float4*)(orow + i * 256))[0] = o0;
        ((float4*)(orow + i * 256))[1] = o1;
    }
}

extern "C" void kernel_launch(void* const* d_in, const int* in_sizes, int n_in,
                              void* d_out, int out_size) {
    const float* A = (const float*)d_in[0];
    const float* Bq = (const float*)d_in[1];
    float* O = (float*)d_out;
    int B = in_sizes[0] / 1024;          // [B, 4, 256]
    dim3 grid((B + 7) / 8);
    nalu_kernel<<<grid, 256>>>(A, Bq, O, B);
}

// round 3
// speedup vs baseline: 1.2363x; 1.2363x over previous
#include <cuda_runtime.h>

#define FULL 0xffffffffu

// Softmax over 16-lane groups for two values at once (x, y one per lane).
// Max phase packed as truncated-bf16 halves (safe: max is only for exp-range
// control; mx <= true max and within 2^-8 relative, so exp arg <= ~6.25).
__device__ __forceinline__ void softmax16_pair(float x, float y, float &px, float &py) {
    unsigned m = (__float_as_uint(x) & 0xFFFF0000u) | (__float_as_uint(y) >> 16);
    m = __vmaxu2(m, __shfl_xor_sync(FULL, m, 1));
    m = __vmaxu2(m, __shfl_xor_sync(FULL, m, 2));
    m = __vmaxu2(m, __shfl_xor_sync(FULL, m, 4));
    m = __vmaxu2(m, __shfl_xor_sync(FULL, m, 8));
    float mx = __uint_as_float(m & 0xFFFF0000u);
    float my = __uint_as_float(m << 16);
    float ex = __expf(100.f * (x - mx));
    float ey = __expf(100.f * (y - my));
    float sx = ex, sy = ey;
    sx += __shfl_xor_sync(FULL, sx, 1);  sy += __shfl_xor_sync(FULL, sy, 1);
    sx += __shfl_xor_sync(FULL, sx, 2);  sy += __shfl_xor_sync(FULL, sy, 2);
    sx += __shfl_xor_sync(FULL, sx, 4);  sy += __shfl_xor_sync(FULL, sy, 4);
    sx += __shfl_xor_sync(FULL, sx, 8);  sy += __shfl_xor_sync(FULL, sy, 8);
    px = __fdividef(ex, sx);
    py = __fdividef(ey, sy);
}

// Cyclic convolution u[s] = sum_j pa[(s-j)&15]*pb[j], pa on lanes 0-15 of p,
// pb on lanes 16-31. Split: lower half does taps j=0..7, upper j=8..15
// (upper's rotation register starts offset by 8), combined with one xor-16.
// Result identical on all 32 lanes: u[lane&15].
__device__ __forceinline__ float conv_u(float p, int srcInit, int srcRot, int cbase) {
    float qa = __shfl_sync(FULL, p, srcInit);
    float acc = 0.f;
#pragma unroll
    for (int j = 0; j < 8; j++) {
        float bj = __shfl_sync(FULL, p, cbase + j);
        acc = fmaf(qa, bj, acc);
        if (j < 7) qa = __shfl_sync(FULL, qa, srcRot);
    }
    return acc + __shfl_xor_sync(FULL, acc, 16);
}

// R0 = sum_{i+j>=16} pa_i*pb_j for BOTH convs of a byte in one stream:
// pbH's suffix scan runs on the lower half, pbL's on the upper half.
// Results broadcast to all lanes.
__device__ __forceinline__ void r0_pair(float pL, float pH, bool lo, int l15,
                                        int srcG, int lane, float &R0L, float &R0H) {
    float xh = __shfl_xor_sync(FULL, pH, 16);        // pbH -> lower half
    float w  = lo ? xh : pL;                         // lower: pbH[s], upper: pbL[s]
#pragma unroll
    for (int d = 1; d <= 8; d <<= 1) {               // suffix sums within 16-groups
        float t = __shfl_sync(FULL, w, lane + d);
        if (l15 + d < 16) w += t;
    }
    float g = __shfl_sync(FULL, w, srcG);            // Tb((16-i)&15), half-matched
    float paUp = __shfl_sync(FULL, pL, l15);         // paL replicated to upper half
    float prod = (lo ? pH : paUp) * g;               // lower: paH_i*TbH, upper: paL_i*TbL
    if (l15 == 0) prod = 0.f;                        // i=0 term is Tb(16)=0
    prod += __shfl_xor_sync(FULL, prod, 1);
    prod += __shfl_xor_sync(FULL, prod, 2);
    prod += __shfl_xor_sync(FULL, prod, 4);
    prod += __shfl_xor_sync(FULL, prod, 8);
    float xr = __shfl_xor_sync(FULL, prod, 16);
    R0H = lo ? prod : xr;
    R0L = lo ? xr : prod;
}

// One warp per batch element, 8 warps/block, zero shared memory, zero barriers.
__global__ void __launch_bounds__(256) nalu_kernel(
        const float* __restrict__ A, const float* __restrict__ Bq,
        float* __restrict__ O, int B) {
    const int lane = threadIdx.x & 31;
    const int n = blockIdx.x * 8 + (threadIdx.x >> 5);
    if (n >= B) return;

    const bool lo   = lane < 16;
    const int  l15  = lane & 15;
    const int srcRot  = ((lane - 1) & 15) | (lane & 16);   // rotate-down within 16-group
    const int srcInit = (lane - ((lane >> 1) & 8)) & 15;   // pa[s] / pa[(s-8)&15]
    const int cbase   = 16 + ((lane >> 1) & 8);            // pb[j] / pb[j+8] broadcast base
    const int srcQ    = (l15 >> 2) | (lane & 16);          // low-sum distribute source
    const int srcH    = 4 * (lane & 7);                    // high-sum distribute source
    const int srcG    = ((16 - l15) & 15) | (lane & 16);   // suffix gather source
    const int srcV    = (l15 + 15) & 15;                   // v[s] = u[(s-1)&15]

    const float4* a4 = (const float4*)(A  + (size_t)n * 1024);
    const float4* b4 = (const float4*)(Bq + (size_t)n * 1024);

    float uL[4], uH[4], r0L[4], r0H[4];

#pragma unroll
    for (int i = 0; i < 4; i++) {
        float4 av0 = a4[i * 64 + lane];
        float4 av1 = a4[i * 64 + 32 + lane];
        float4 bv0 = b4[i * 64 + lane];
        float4 bv1 = b4[i * 64 + 32 + lane];

        // ---- low-nibble sums: la[l] = sum_h x[16h+l] ----
        // lane L's 8 elements cover low quad 4*(L&3)+{0..3} (twice).
        float la0 = av0.x + av1.x, la1 = av0.y + av1.y;
        float la2 = av0.z + av1.z, la3 = av0.w + av1.w;
        float lb0 = bv0.x + bv1.x, lb1 = bv0.y + bv1.y;
        float lb2 = bv0.z + bv1.z, lb3 = bv0.w + bv1.w;
        // merge a->lower/b->upper, fold the cross half with one xor-16
        float m0 = lo ? la0 : lb0, n0 = lo ? lb0 : la0;
        float m1 = lo ? la1 : lb1, n1 = lo ? lb1 : la1;
        float m2 = lo ? la2 : lb2, n2 = lo ? lb2 : la2;
        float m3 = lo ? la3 : lb3, n3 = lo ? lb3 : la3;
        float t0 = m0 + __shfl_xor_sync(FULL, n0, 16);
        float t1 = m1 + __shfl_xor_sync(FULL, n1, 16);
        float t2 = m2 + __shfl_xor_sync(FULL, n2, 16);
        float t3 = m3 + __shfl_xor_sync(FULL, n3, 16);
        t0 += __shfl_xor_sync(FULL, t0, 4);  t0 += __shfl_xor_sync(FULL, t0, 8);
        t1 += __shfl_xor_sync(FULL, t1, 4);  t1 += __shfl_xor_sync(FULL, t1, 8);
        t2 += __shfl_xor_sync(FULL, t2, 4);  t2 += __shfl_xor_sync(FULL, t2, 8);
        t3 += __shfl_xor_sync(FULL, t3, 4);  t3 += __shfl_xor_sync(FULL, t3, 8);
        float q0 = __shfl_sync(FULL, t0, srcQ);
        float q1 = __shfl_sync(FULL, t1, srcQ);
        float q2 = __shfl_sync(FULL, t2, srcQ);
        float q3 = __shfl_sync(FULL, t3, srcQ);
        float lv = (lane & 2) ? ((lane & 1) ? q3 : q2)
                              : ((lane & 1) ? q1 : q0);

        // ---- high-nibble sums: ha[h] = sum_l x[16h+l] ----
        // lane L's av0 all share h=L>>2; av1 share h=8+(L>>2). Reduce over quads.
        float hp0a = (av0.x + av0.y) + (av0.z + av0.w);
        float hp1a = (av1.x + av1.y) + (av1.z + av1.w);
        float hp0b = (bv0.x + bv0.y) + (bv0.z + bv0.w);
        float hp1b = (bv1.x + bv1.y) + (bv1.z + bv1.w);
        hp0a += __shfl_xor_sync(FULL, hp0a, 1);  hp0a += __shfl_xor_sync(FULL, hp0a, 2);
        hp1a += __shfl_xor_sync(FULL, hp1a, 1);  hp1a += __shfl_xor_sync(FULL, hp1a, 2);
        hp0b += __shfl_xor_sync(FULL, hp0b, 1);  hp0b += __shfl_xor_sync(FULL, hp0b, 2);
        hp1b += __shfl_xor_sync(FULL, hp1b, 1);  hp1b += __shfl_xor_sync(FULL, hp1b, 2);
        float w0a = __shfl_sync(FULL, hp0a, srcH);
        float w1a = __shfl_sync(FULL, hp1a, srcH);
        float w0b = __shfl_sync(FULL, hp0b, srcH);
        float w1b = __shfl_sync(FULL, hp1b, srcH);
        float hv = lo ? ((lane & 8) ? w1a : w0a)
                      : ((lane & 8) ? w1b : w0b);

        // ---- softmaxes (a on lanes 0-15, b on 16-31) ----
        float ph, pl;
        softmax16_pair(hv, lv, ph, pl);

        // ---- cyclic convs + carry tails ----
        uL[i] = conv_u(pl, srcInit, srcRot, cbase);
        uH[i] = conv_u(ph, srcInit, srcRot, cbase);
        r0_pair(pl, ph, lo, l15, srcG, lane, r0L[i], r0H[i]);
    }

    // ---- serial ripple-carry chain + outer-product outputs ----
    float c1 = 0.f;  // P(carry=1); carry starts one-hot [1,0]
    float* orow = O + (size_t)n * 1024 + lane * 8;
#pragma unroll
    for (int i = 0; i < 4; i++) {
        float vl   = __shfl_sync(FULL, uL[i], srcV);
        float u15L = __shfl_sync(FULL, uL[i], 15);
        float vh   = __shfl_sync(FULL, uH[i], srcV);
        float u15H = __shfl_sync(FULL, uH[i], 15);

        float pc1 = __fdividef(1.f, 1.f + __expf(100.f * (1.f - 2.f * c1)));
        float pc0 = 1.f - pc1;
        float sl = fmaf(pc0, uL[i], pc1 * vl);
        c1 = fmaf(pc0, r0L[i], pc1 * (r0L[i] + u15L));

        pc1 = __fdividef(1.f, 1.f + __expf(100.f * (1.f - 2.f * c1)));
        pc0 = 1.f - pc1;
        float sh = fmaf(pc0, uH[i], pc1 * vh);
        c1 = fmaf(pc0, r0H[i], pc1 * (r0H[i] + u15H));

        float psh, psl;
        softmax16_pair(sh, sl, psh, psl);

        // out[h*16+l] = psh[h]*psl[l]; lane covers h = lane>>1, l in [(lane&1)*8, +8)
        float hvv = __shfl_sync(FULL, psh, lane >> 1);
        int lb = (lane & 1) * 8;
        float4 o0, o1;
        o0.x = hvv * __shfl_sync(FULL, psl, lb + 0);
        o0.y = hvv * __shfl_sync(FULL, psl, lb + 1);
        o0.z = hvv * __shfl_sync(FULL, psl, lb + 2);
        o0.w = hvv * __shfl_sync(FULL, psl, lb + 3);
        o1.x = hvv * __shfl_sync(FULL, psl, lb + 4);
        o1.y = hvv * __shfl_sync(FULL, psl, lb + 5);
        o1.z = hvv * __shfl_sync(FULL, psl, lb + 6);
        o1.w = hvv * __shfl_sync(FULL, psl, lb + 7);
        ((float4*)(orow + i * 256))[0] = o0;
        ((float4*)(orow + i * 256))[1] = o1;
    }
}

extern "C" void kernel_launch(void* const* d_in, const int* in_sizes, int n_in,
                              void* d_out, int out_size) {
    const float* A  = (const float*)d_in[0];
    const float* Bq = (const float*)d_in[1];
    float* O = (float*)d_out;
    int B = in_sizes[0] / 1024;          // [B, 4, 256]
    dim3 grid((B + 7) / 8);
    nalu_kernel<<<grid, 256>>>(A, Bq, O, B);
}

// round 5
// speedup vs baseline: 1.3312x; 1.0768x over previous
#include <cuda_runtime.h>

#define FULL 0xffffffffu

// Softmax over 16-lane groups for two values at once (x, y one per lane).
// Max phase packed as truncated-bf16 halves (max only controls exp range;
// softmax is shift-invariant, so result is exact).
__device__ __forceinline__ void softmax16_pair(float x, float y, float &px, float &py) {
    unsigned m = (__float_as_uint(x) & 0xFFFF0000u) | (__float_as_uint(y) >> 16);
    m = __vmaxu2(m, __shfl_xor_sync(FULL, m, 1));
    m = __vmaxu2(m, __shfl_xor_sync(FULL, m, 2));
    m = __vmaxu2(m, __shfl_xor_sync(FULL, m, 4));
    m = __vmaxu2(m, __shfl_xor_sync(FULL, m, 8));
    float mx = __uint_as_float(m & 0xFFFF0000u);
    float my = __uint_as_float(m << 16);
    float ex = __expf(100.f * (x - mx));
    float ey = __expf(100.f * (y - my));
    float sx = ex, sy = ey;
    sx += __shfl_xor_sync(FULL, sx, 1);  sy += __shfl_xor_sync(FULL, sy, 1);
    sx += __shfl_xor_sync(FULL, sx, 2);  sy += __shfl_xor_sync(FULL, sy, 2);
    sx += __shfl_xor_sync(FULL, sx, 4);  sy += __shfl_xor_sync(FULL, sy, 4);
    sx += __shfl_xor_sync(FULL, sx, 8);  sy += __shfl_xor_sync(FULL, sy, 8);
    px = __fdividef(ex, sx);
    py = __fdividef(ey, sy);
}

// Single-stream softmax over each 16-lane group (one value per lane).
__device__ __forceinline__ float softmax16(float x) {
    float m = x;
    m = fmaxf(m, __shfl_xor_sync(FULL, m, 1));
    m = fmaxf(m, __shfl_xor_sync(FULL, m, 2));
    m = fmaxf(m, __shfl_xor_sync(FULL, m, 4));
    m = fmaxf(m, __shfl_xor_sync(FULL, m, 8));
    float e = __expf(100.f * (x - m));
    float s = e;
    s += __shfl_xor_sync(FULL, s, 1);
    s += __shfl_xor_sync(FULL, s, 2);
    s += __shfl_xor_sync(FULL, s, 4);
    s += __shfl_xor_sync(FULL, s, 8);
    return __fdividef(e, s);
}

// R0 = sum_{i+j>=16} pa_i*pb_j for BOTH convs of a byte in one stream:
// pbH's suffix scan runs on the lower half, pbL's on the upper half.
// Results broadcast to all lanes.
__device__ __forceinline__ void r0_pair(float pL, float pH, bool lo, int l15,
                                        int srcG, int lane, float &R0L, float &R0H) {
    float xh = __shfl_xor_sync(FULL, pH, 16);        // pbH -> lower half
    float w  = lo ? xh : pL;                         // lower: pbH[s], upper: pbL[s]
#pragma unroll
    for (int d = 1; d <= 8; d <<= 1) {               // suffix sums within 16-groups
        float t = __shfl_sync(FULL, w, lane + d);
        if (l15 + d < 16) w += t;
    }
    float g = __shfl_sync(FULL, w, srcG);            // Tb((16-i)&15), half-matched
    float paUp = __shfl_sync(FULL, pL, l15);         // paL replicated to upper half
    float prod = (lo ? pH : paUp) * g;               // lower: paH_i*TbH, upper: paL_i*TbL
    if (l15 == 0) prod = 0.f;                        // i=0 term is Tb(16)=0
    prod += __shfl_xor_sync(FULL, prod, 1);
    prod += __shfl_xor_sync(FULL, prod, 2);
    prod += __shfl_xor_sync(FULL, prod, 4);
    prod += __shfl_xor_sync(FULL, prod, 8);
    float xr = __shfl_xor_sync(FULL, prod, 16);
    R0H = lo ? prod : xr;
    R0L = lo ? xr : prod;
}

// One warp per batch element, 8 warps/block, zero smem, zero barriers.
// Fused: sums -> softmax -> conv (L on lower half, H on upper half, one
// shuffle stream) -> carry update -> output, per byte.
__global__ void __launch_bounds__(256, 7) nalu_kernel(
        const float* __restrict__ A, const float* __restrict__ Bq,
        float* __restrict__ O, int B) {
    const int lane = threadIdx.x & 31;
    const int n = blockIdx.x * 8 + (threadIdx.x >> 5);
    if (n >= B) return;

    const bool lo   = lane < 16;
    const int  l15  = lane & 15;
    const int hi16    = lane & 16;
    const int srcRot  = ((lane - 1) & 15) | hi16;          // rotate-down within 16-group
    const int srcQ    = (l15 >> 2) | hi16;                 // low-sum distribute source
    const int srcH    = 4 * (lane & 7);                    // high-sum distribute source
    const int srcG    = ((16 - l15) & 15) | hi16;          // suffix gather source
    const int srcV    = ((l15 + 15) & 15) | hi16;          // v[s] = u[(s-1)&15], per half
    const int srcHV   = 16 + (lane >> 1);                  // outer-product psh source

    const float4* a4 = (const float4*)(A  + (size_t)n * 1024);
    const float4* b4 = (const float4*)(Bq + (size_t)n * 1024);
    float* orow = O + (size_t)n * 1024 + lane * 8;

    float c1 = 0.f;  // P(carry=1); carry starts one-hot [1,0]

#pragma unroll 1
    for (int i = 0; i < 4; i++) {
        float4 av0 = a4[i * 64 + lane];
        float4 av1 = a4[i * 64 + 32 + lane];
        float4 bv0 = b4[i * 64 + lane];
        float4 bv1 = b4[i * 64 + 32 + lane];

        // ---- low-nibble sums: la[l] = sum_h x[16h+l] ----
        float la0 = av0.x + av1.x, la1 = av0.y + av1.y;
        float la2 = av0.z + av1.z, la3 = av0.w + av1.w;
        float lb0 = bv0.x + bv1.x, lb1 = bv0.y + bv1.y;
        float lb2 = bv0.z + bv1.z, lb3 = bv0.w + bv1.w;
        float m0 = lo ? la0 : lb0, n0 = lo ? lb0 : la0;
        float m1 = lo ? la1 : lb1, n1 = lo ? lb1 : la1;
        float m2 = lo ? la2 : lb2, n2 = lo ? lb2 : la2;
        float m3 = lo ? la3 : lb3, n3 = lo ? lb3 : la3;
        float t0 = m0 + __shfl_xor_sync(FULL, n0, 16);
        float t1 = m1 + __shfl_xor_sync(FULL, n1, 16);
        float t2 = m2 + __shfl_xor_sync(FULL, n2, 16);
        float t3 = m3 + __shfl_xor_sync(FULL, n3, 16);
        t0 += __shfl_xor_sync(FULL, t0, 4);  t0 += __shfl_xor_sync(FULL, t0, 8);
        t1 += __shfl_xor_sync(FULL, t1, 4);  t1 += __shfl_xor_sync(FULL, t1, 8);
        t2 += __shfl_xor_sync(FULL, t2, 4);  t2 += __shfl_xor_sync(FULL, t2, 8);
        t3 += __shfl_xor_sync(FULL, t3, 4);  t3 += __shfl_xor_sync(FULL, t3, 8);
        float q0 = __shfl_sync(FULL, t0, srcQ);
        float q1 = __shfl_sync(FULL, t1, srcQ);
        float q2 = __shfl_sync(FULL, t2, srcQ);
        float q3 = __shfl_sync(FULL, t3, srcQ);
        float lv = (lane & 2) ? ((lane & 1) ? q3 : q2)
                              : ((lane & 1) ? q1 : q0);

        // ---- high-nibble sums: ha[h] = sum_l x[16h+l] ----
        float hp0a = (av0.x + av0.y) + (av0.z + av0.w);
        float hp1a = (av1.x + av1.y) + (av1.z + av1.w);
        float hp0b = (bv0.x + bv0.y) + (bv0.z + bv0.w);
        float hp1b = (bv1.x + bv1.y) + (bv1.z + bv1.w);
        hp0a += __shfl_xor_sync(FULL, hp0a, 1);  hp0a += __shfl_xor_sync(FULL, hp0a, 2);
        hp1a += __shfl_xor_sync(FULL, hp1a, 1);  hp1a += __shfl_xor_sync(FULL, hp1a, 2);
        hp0b += __shfl_xor_sync(FULL, hp0b, 1);  hp0b += __shfl_xor_sync(FULL, hp0b, 2);
        hp1b += __shfl_xor_sync(FULL, hp1b, 1);  hp1b += __shfl_xor_sync(FULL, hp1b, 2);
        float w0a = __shfl_sync(FULL, hp0a, srcH);
        float w1a = __shfl_sync(FULL, hp1a, srcH);
        float w0b = __shfl_sync(FULL, hp0b, srcH);
        float w1b = __shfl_sync(FULL, hp1b, srcH);
        float hv = lo ? ((lane & 8) ? w1a : w0a)
                      : ((lane & 8) ? w1b : w0b);

        // ---- input softmaxes: pl/ph hold pa (lanes 0-15) | pb (16-31) ----
        float ph, pl;
        softmax16_pair(hv, lv, ph, pl);

        // ---- carry tails (needs a/b layout) ----
        float r0L, r0H;
        r0_pair(pl, ph, lo, l15, srcG, lane, r0L, r0H);

        // ---- merged cyclic convs: conv-L on lower half, conv-H on upper ----
        // c: lane s -> pbL[s], lane 16+s -> pbH[s]
        float cshf = __shfl_xor_sync(FULL, pl, 16);
        float creg = lo ? cshf : ph;
        // q: lane s -> paL[s], lane 16+s -> paH[s]
        float qshf = __shfl_sync(FULL, ph, l15);
        float q    = lo ? pl : qshf;
        float u = 0.f;
#pragma unroll
        for (int j = 0; j < 16; j++) {
            float bj = __shfl_sync(FULL, creg, j | hi16);
            u = fmaf(q, bj, u);
            if (j < 15) q = __shfl_sync(FULL, q, srcRot);
        }
        // u: uL[s] on lane s, uH[s] on lane 16+s

        float v    = __shfl_sync(FULL, u, srcV);   // vl lower | vh upper
        float u15L = __shfl_sync(FULL, u, 15);
        float u15H = __shfl_sync(FULL, u, 31);

        // ---- serial carry chain (lane-uniform scalars) ----
        float pc1L = __fdividef(1.f, 1.f + __expf(100.f * (1.f - 2.f * c1)));
        float pc0L = 1.f - pc1L;
        c1 = fmaf(pc0L, r0L, pc1L * (r0L + u15L));
        float pc1H = __fdividef(1.f, 1.f + __expf(100.f * (1.f - 2.f * c1)));
        float pc0H = 1.f - pc1H;
        c1 = fmaf(pc0H, r0H, pc1H * (r0H + u15H));

        // per-half blended sums: sl on lower half, sh on upper half
        float x = lo ? fmaf(pc0L, u, pc1L * v)
                     : fmaf(pc0H, u, pc1H * v);

        // ---- output softmax: psl on lower half, psh on upper half ----
        float p_out = softmax16(x);

        // out[h*16+l] = psh[h]*psl[l]; lane covers h = lane>>1, l in [(lane&1)*8, +8)
        float hvv = __shfl_sync(FULL, p_out, srcHV);
        int lb = (lane & 1) * 8;
        float4 o0, o1;
        o0.x = hvv * __shfl_sync(FULL, p_out, lb + 0);
        o0.y = hvv * __shfl_sync(FULL, p_out, lb + 1);
        o0.z = hvv * __shfl_sync(FULL, p_out, lb + 2);
        o0.w = hvv * __shfl_sync(FULL, p_out, lb + 3);
        o1.x = hvv * __shfl_sync(FULL, p_out, lb + 4);
        o1.y = hvv * __shfl_sync(FULL, p_out, lb + 5);
        o1.z = hvv * __shfl_sync(FULL, p_out, lb + 6);
        o1.w = hvv * __shfl_sync(FULL, p_out, lb + 7);
        ((float4*)(orow + i * 256))[0] = o0;
        ((float4*)(orow + i * 256))[1] = o1;
    }
}

extern "C" void kernel_launch(void* const* d_in, const int* in_sizes, int n_in,
                              void* d_out, int out_size) {
    const float* A  = (const float*)d_in[0];
    const float* Bq = (const float*)d_in[1];
    float* O = (float*)d_out;
    int B = in_sizes[0] / 1024;          // [B, 4, 256]
    dim3 grid((B + 7) / 8);
    nalu_kernel<<<grid, 256>>>(A, Bq, O, B);
}

// round 7
// speedup vs baseline: 1.4174x; 1.0647x over previous
#include <cuda_runtime.h>

#define FULL 0xffffffffu

// Softmax over 16-lane groups for two values at once (x, y one per lane).
// Max phase packed as truncated-bf16 halves (max only controls exp range;
// softmax is shift-invariant, so result is exact).
__device__ __forceinline__ void softmax16_pair(float x, float y, float &px, float &py) {
    unsigned m = (__float_as_uint(x) & 0xFFFF0000u) | (__float_as_uint(y) >> 16);
    m = __vmaxu2(m, __shfl_xor_sync(FULL, m, 1));
    m = __vmaxu2(m, __shfl_xor_sync(FULL, m, 2));
    m = __vmaxu2(m, __shfl_xor_sync(FULL, m, 4));
    m = __vmaxu2(m, __shfl_xor_sync(FULL, m, 8));
    float mx = __uint_as_float(m & 0xFFFF0000u);
    float my = __uint_as_float(m << 16);
    float ex = __expf(100.f * (x - mx));
    float ey = __expf(100.f * (y - my));
    float sx = ex, sy = ey;
    sx += __shfl_xor_sync(FULL, sx, 1);  sy += __shfl_xor_sync(FULL, sy, 1);
    sx += __shfl_xor_sync(FULL, sx, 2);  sy += __shfl_xor_sync(FULL, sy, 2);
    sx += __shfl_xor_sync(FULL, sx, 4);  sy += __shfl_xor_sync(FULL, sy, 4);
    sx += __shfl_xor_sync(FULL, sx, 8);  sy += __shfl_xor_sync(FULL, sy, 8);
    px = __fdividef(ex, sx);
    py = __fdividef(ey, sy);
}

// Single-stream softmax over each 16-lane group (one value per lane).
__device__ __forceinline__ float softmax16(float x) {
    float m = x;
    m = fmaxf(m, __shfl_xor_sync(FULL, m, 1));
    m = fmaxf(m, __shfl_xor_sync(FULL, m, 2));
    m = fmaxf(m, __shfl_xor_sync(FULL, m, 4));
    m = fmaxf(m, __shfl_xor_sync(FULL, m, 8));
    float e = __expf(100.f * (x - m));
    float s = e;
    s += __shfl_xor_sync(FULL, s, 1);
    s += __shfl_xor_sync(FULL, s, 2);
    s += __shfl_xor_sync(FULL, s, 4);
    s += __shfl_xor_sync(FULL, s, 8);
    return __fdividef(e, s);
}

// One warp per batch element, 8 warps/block, zero smem, zero barriers.
__global__ void __launch_bounds__(256, 7) nalu_kernel(
        const float* __restrict__ A, const float* __restrict__ Bq,
        float* __restrict__ O, int B) {
    const int lane = threadIdx.x & 31;
    const int n = blockIdx.x * 8 + (threadIdx.x >> 5);
    if (n >= B) return;

    const bool lo   = lane < 16;
    const int  l15  = lane & 15;
    const int  hi16 = lane & 16;
    const bool b0 = lane & 1, b1 = lane & 2, b2 = lane & 4, b3 = lane & 8;
    const int srcRot = ((lane - 1) & 15) | hi16;            // rotate-down within 16-group
    // low-sum inverse permutation: lane s holds col c(s)=4(s&3)+2*bit2(s)+bit3(s)
    const int srcL   = ((l15 >> 2) | ((l15 & 2) << 1) | ((l15 & 1) << 3)) | hi16;
    // high-sum distribute: lane 4r+{0,1,2,3} = {ha[r], hb[r], ha[8+r], hb[8+r]}
    const int srcH   = 4 * (l15 & 7) + 2 * ((l15 >> 3) & 1) + (lo ? 0 : 1);
    const int srcV   = ((l15 + 15) & 15) | hi16;            // v[s] = u[(s-1)&15], per half
    const int srcHV  = 16 + (lane >> 1);                    // outer-product psh source

    const float4* a4 = (const float4*)(A  + (size_t)n * 1024);
    const float4* b4 = (const float4*)(Bq + (size_t)n * 1024);
    float* orow = O + (size_t)n * 1024 + lane * 8;

    float c1 = 0.f;  // P(carry=1); carry starts one-hot [1,0]

#pragma unroll 1
    for (int i = 0; i < 4; i++) {
        float4 av0 = a4[i * 64 + lane];
        float4 av1 = a4[i * 64 + 32 + lane];
        float4 bv0 = b4[i * 64 + lane];
        float4 bv1 = b4[i * 64 + 32 + lane];

        // ---- low-nibble sums via reduce-scatter ----
        float la0 = av0.x + av1.x, la1 = av0.y + av1.y;
        float la2 = av0.z + av1.z, la3 = av0.w + av1.w;
        float lb0 = bv0.x + bv1.x, lb1 = bv0.y + bv1.y;
        float lb2 = bv0.z + bv1.z, lb3 = bv0.w + bv1.w;
        // stage xor16: lower keeps a-side, upper keeps b-side
        float t0 = (lo ? la0 : lb0) + __shfl_xor_sync(FULL, lo ? lb0 : la0, 16);
        float t1 = (lo ? la1 : lb1) + __shfl_xor_sync(FULL, lo ? lb1 : la1, 16);
        float t2 = (lo ? la2 : lb2) + __shfl_xor_sync(FULL, lo ? lb2 : la2, 16);
        float t3 = (lo ? la3 : lb3) + __shfl_xor_sync(FULL, lo ? lb3 : la3, 16);
        // stage xor4: b2=0 keeps (t0,t1), b2=1 keeps (t2,t3)
        float ra = __shfl_xor_sync(FULL, b2 ? t0 : t2, 4);
        float rb = __shfl_xor_sync(FULL, b2 ? t1 : t3, 4);
        float pp = (b2 ? t2 : t0) + ra;
        float qq = (b2 ? t3 : t1) + rb;
        // stage xor8: b3=0 keeps pp, b3=1 keeps qq
        float rc = __shfl_xor_sync(FULL, b3 ? pp : qq, 8);
        float lres = (b3 ? qq : pp) + rc;
        float lv = __shfl_sync(FULL, lres, srcL);

        // ---- high-nibble sums via reduce-scatter ----
        float hp0a = (av0.x + av0.y) + (av0.z + av0.w);   // a row L>>2
        float hp1a = (av1.x + av1.y) + (av1.z + av1.w);   // a row 8+(L>>2)
        float hp0b = (bv0.x + bv0.y) + (bv0.z + bv0.w);
        float hp1b = (bv1.x + bv1.y) + (bv1.z + bv1.w);
        // stage xor1: b0=0 keeps a-pair, b0=1 keeps b-pair
        float ga = __shfl_xor_sync(FULL, b0 ? hp0a : hp0b, 1);
        float gb = __shfl_xor_sync(FULL, b0 ? hp1a : hp1b, 1);
        float hpA = (b0 ? hp0b : hp0a) + ga;
        float hpB = (b0 ? hp1b : hp1a) + gb;
        // stage xor2: b1=0 keeps hpA, b1=1 keeps hpB
        float gc = __shfl_xor_sync(FULL, b1 ? hpA : hpB, 2);
        float hres = (b1 ? hpB : hpA) + gc;
        float hv = __shfl_sync(FULL, hres, srcH);

        // ---- input softmaxes: pl/ph hold pa (lanes 0-15) | pb (16-31) ----
        float ph, pl;
        softmax16_pair(hv, lv, ph, pl);

        // ---- merged cyclic convs with embedded wrap accumulator ----
        // creg: lane s -> pbL[s], lane 16+s -> pbH[s]
        float cshf = __shfl_xor_sync(FULL, pl, 16);
        float creg = lo ? cshf : ph;
        // qv:   lane s -> paL[s], lane 16+s -> paH[s]
        float qshf = __shfl_sync(FULL, ph, l15);
        float qv   = lo ? pl : qshf;
        float u1 = 0.f, u2 = 0.f;   // u1: j<=s taps, u2: j>s (wrap) taps
        {
            float bj = __shfl_sync(FULL, creg, 0 | hi16);   // j=0: always j<=s
            u1 = qv * bj;
            qv = __shfl_sync(FULL, qv, srcRot);
        }
#pragma unroll
        for (int j = 1; j < 16; j++) {
            float bj = __shfl_sync(FULL, creg, j | hi16);
            if (j <= l15) u1 = fmaf(qv, bj, u1);
            else          u2 = fmaf(qv, bj, u2);
            if (j < 15) qv = __shfl_sync(FULL, qv, srcRot);
        }
        float u = u1 + u2;
        // u: uL[s] on lane s, uH[s] on lane 16+s
        // R0 = sum_s u2[s] per half
        u2 += __shfl_xor_sync(FULL, u2, 1);
        u2 += __shfl_xor_sync(FULL, u2, 2);
        u2 += __shfl_xor_sync(FULL, u2, 4);
        u2 += __shfl_xor_sync(FULL, u2, 8);
        float wx = __shfl_xor_sync(FULL, u2, 16);
        float r0L = lo ? u2 : wx;
        float r0H = lo ? wx : u2;

        float v    = __shfl_sync(FULL, u, srcV);   // vl lower | vh upper
        float u15L = __shfl_sync(FULL, u, 15);
        float u15H = __shfl_sync(FULL, u, 31);

        // ---- serial carry chain (lane-uniform scalars) ----
        float pc1L = __fdividef(1.f, 1.f + __expf(100.f * (1.f - 2.f * c1)));
        float pc0L = 1.f - pc1L;
        c1 = fmaf(pc0L, r0L, pc1L * (r0L + u15L));
        float pc1H = __fdividef(1.f, 1.f + __expf(100.f * (1.f - 2.f * c1)));
        float pc0H = 1.f - pc1H;
        c1 = fmaf(pc0H, r0H, pc1H * (r0H + u15H));

        // per-half blended sums: sl on lower half, sh on upper half
        float x = lo ? fmaf(pc0L, u, pc1L * v)
                     : fmaf(pc0H, u, pc1H * v);

        // ---- output softmax: psl on lower half, psh on upper half ----
        float p_out = softmax16(x);

        // out[h*16+l] = psh[h]*psl[l]; lane covers h = lane>>1, l in [(lane&1)*8, +8)
        float hvv = __shfl_sync(FULL, p_out, srcHV);
        int lb = (lane & 1) * 8;
        float4 o0, o1;
        o0.x = hvv * __shfl_sync(FULL, p_out, lb + 0);
        o0.y = hvv * __shfl_sync(FULL, p_out, lb + 1);
        o0.z = hvv * __shfl_sync(FULL, p_out, lb + 2);
        o0.w = hvv * __shfl_sync(FULL, p_out, lb + 3);
        o1.x = hvv * __shfl_sync(FULL, p_out, lb + 4);
        o1.y = hvv * __shfl_sync(FULL, p_out, lb + 5);
        o1.z = hvv * __shfl_sync(FULL, p_out, lb + 6);
        o1.w = hvv * __shfl_sync(FULL, p_out, lb + 7);
        ((float4*)(orow + i * 256))[0] = o0;
        ((float4*)(orow + i * 256))[1] = o1;
    }
}

extern "C" void kernel_launch(void* const* d_in, const int* in_sizes, int n_in,
                              void* d_out, int out_size) {
    const float* A  = (const float*)d_in[0];
    const float* Bq = (const float*)d_in[1];
    float* O = (float*)d_out;
    int B = in_sizes[0] / 1024;          // [B, 4, 256]
    dim3 grid((B + 7) / 8);
    nalu_kernel<<<grid, 256>>>(A, Bq, O, B);
}